// round 4
// baseline (speedup 1.0000x reference)
#include <cuda_runtime.h>
#include <math.h>

// Problem constants
#define N_IMG   64
#define A_CH    512      // input channels (K)
#define M_POSE  512      // B*16 pose output rows
#define B_CAPS  32       // activation output rows
#define M_TOT   544      // 512 + 32
#define HW      1024     // 32*32 pixels per image

// GEMM tiling
#define BM 128
#define BN 128
#define BK 16
#define NKT (A_CH / BK)  // 32 K-tiles

// Packed fused weight matrix [M_TOT, A_CH] and bias [M_TOT] (scratch: __device__ globals)
__device__ float g_W[M_TOT * A_CH];
__device__ float g_bias[M_TOT];

__global__ void pack_weights(const float* __restrict__ Wp, const float* __restrict__ bp,
                             const float* __restrict__ Wa, const float* __restrict__ ba) {
    int total = M_TOT * A_CH;
    for (int i = blockIdx.x * blockDim.x + threadIdx.x; i < total;
         i += gridDim.x * blockDim.x) {
        int o = i / A_CH;
        int a = i - o * A_CH;
        g_W[i] = (o < M_POSE) ? Wp[o * A_CH + a] : Wa[(o - M_POSE) * A_CH + a];
    }
    int t = blockIdx.x * blockDim.x + threadIdx.x;
    if (t < M_TOT) g_bias[t] = (t < M_POSE) ? bp[t] : ba[t - M_POSE];
}

// One CTA computes a 128(M) x 128(N) tile of Y[n] = Wc @ X[n].
// blockIdx.x: M-tile (0..4, last is partial: rows 512..543)
// blockIdx.y: HW-tile (0..7)
// blockIdx.z: image n (0..63)
__global__ __launch_bounds__(256, 2)
void caps_gemm(const float* __restrict__ x, float* __restrict__ out) {
    // As transposed [k][m], padded to keep 16B alignment and spread banks
    __shared__ float As[2][BK][BM + 4];
    __shared__ float Bs[2][BK][BN];

    const int n_img = blockIdx.z;
    const int m0    = blockIdx.x * BM;
    const int hw0   = blockIdx.y * BN;
    const int tid   = threadIdx.x;
    const int tx    = tid & 15;   // N direction
    const int ty    = tid >> 4;   // M direction

    const float* __restrict__ xb = x + (size_t)n_img * A_CH * HW;

    // ---- global tile loaders (2 x float4 each per operand per thread) ----
    // W tile: BM(128) rows x BK(16) cols = 512 float4; loadIdx -> row = li>>2, k-col = (li&3)*4
    // X tile: BK(16) rows x BN(128) cols = 512 float4; loadIdx -> row = li>>5, n-col = (li&31)*4
    float4 wreg[2], xreg[2];

    const int liw0 = tid * 2;
    const int wrow0 = liw0 >> 2,        wcol0 = (liw0 & 3) * 4;
    const int wrow1 = (liw0 + 1) >> 2,  wcol1 = ((liw0 + 1) & 3) * 4;
    const int xrow0 = liw0 >> 5,        xcol0 = (liw0 & 31) * 4;
    const int xrow1 = (liw0 + 1) >> 5,  xcol1 = ((liw0 + 1) & 31) * 4;

    const bool wval0 = (m0 + wrow0) < M_TOT;
    const bool wval1 = (m0 + wrow1) < M_TOT;

#define LOAD_TILES(k0)                                                              \
    do {                                                                            \
        wreg[0] = wval0 ? *(const float4*)(&g_W[(m0 + wrow0) * A_CH + (k0) + wcol0])\
                        : make_float4(0.f, 0.f, 0.f, 0.f);                          \
        wreg[1] = wval1 ? *(const float4*)(&g_W[(m0 + wrow1) * A_CH + (k0) + wcol1])\
                        : make_float4(0.f, 0.f, 0.f, 0.f);                          \
        xreg[0] = *(const float4*)(&xb[(size_t)((k0) + xrow0) * HW + hw0 + xcol0]); \
        xreg[1] = *(const float4*)(&xb[(size_t)((k0) + xrow1) * HW + hw0 + xcol1]); \
    } while (0)

#define STORE_TILES(buf)                                                            \
    do {                                                                            \
        As[buf][wcol0 + 0][wrow0] = wreg[0].x;                                      \
        As[buf][wcol0 + 1][wrow0] = wreg[0].y;                                      \
        As[buf][wcol0 + 2][wrow0] = wreg[0].z;                                      \
        As[buf][wcol0 + 3][wrow0] = wreg[0].w;                                      \
        As[buf][wcol1 + 0][wrow1] = wreg[1].x;                                      \
        As[buf][wcol1 + 1][wrow1] = wreg[1].y;                                      \
        As[buf][wcol1 + 2][wrow1] = wreg[1].z;                                      \
        As[buf][wcol1 + 3][wrow1] = wreg[1].w;                                      \
        *(float4*)(&Bs[buf][xrow0][xcol0]) = xreg[0];                               \
        *(float4*)(&Bs[buf][xrow1][xcol1]) = xreg[1];                               \
    } while (0)

    float acc[8][8];
#pragma unroll
    for (int i = 0; i < 8; ++i)
#pragma unroll
        for (int j = 0; j < 8; ++j) acc[i][j] = 0.f;

    LOAD_TILES(0);
    STORE_TILES(0);
    __syncthreads();

    int buf = 0;
#pragma unroll 1
    for (int kt = 0; kt < NKT; ++kt) {
        const bool has_next = (kt + 1) < NKT;
        if (has_next) LOAD_TILES((kt + 1) * BK);

#pragma unroll
        for (int k = 0; k < BK; ++k) {
            float4 a0 = *(const float4*)(&As[buf][k][ty * 4]);
            float4 a1 = *(const float4*)(&As[buf][k][64 + ty * 4]);
            float4 b0 = *(const float4*)(&Bs[buf][k][tx * 4]);
            float4 b1 = *(const float4*)(&Bs[buf][k][64 + tx * 4]);
            float a[8] = {a0.x, a0.y, a0.z, a0.w, a1.x, a1.y, a1.z, a1.w};
            float b[8] = {b0.x, b0.y, b0.z, b0.w, b1.x, b1.y, b1.z, b1.w};
#pragma unroll
            for (int i = 0; i < 8; ++i)
#pragma unroll
                for (int j = 0; j < 8; ++j) acc[i][j] = fmaf(a[i], b[j], acc[i][j]);
        }

        if (has_next) {
            STORE_TILES(buf ^ 1);
            __syncthreads();
            buf ^= 1;
        }
    }

    // ---- epilogue: bias add, (sigmoid for act rows), scatter to the two output segments ----
    const size_t pose_base = (size_t)n_img * M_POSE * HW;
    const size_t act_base  = (size_t)N_IMG * M_POSE * HW + (size_t)n_img * B_CAPS * HW;

#pragma unroll
    for (int mi = 0; mi < 2; ++mi) {
#pragma unroll
        for (int i = 0; i < 4; ++i) {
            const int mloc = mi * 64 + ty * 4 + i;
            const int m = m0 + mloc;
            if (m >= M_TOT) continue;
            const float bias = g_bias[m];
#pragma unroll
            for (int ni = 0; ni < 2; ++ni) {
                const int nloc = ni * 64 + tx * 4;
                const int hw = hw0 + nloc;
                float4 v;
                v.x = acc[mi * 4 + i][ni * 4 + 0] + bias;
                v.y = acc[mi * 4 + i][ni * 4 + 1] + bias;
                v.z = acc[mi * 4 + i][ni * 4 + 2] + bias;
                v.w = acc[mi * 4 + i][ni * 4 + 3] + bias;
                if (m < M_POSE) {
                    *(float4*)(&out[pose_base + (size_t)m * HW + hw]) = v;
                } else {
                    v.x = 1.f / (1.f + expf(-v.x));
                    v.y = 1.f / (1.f + expf(-v.y));
                    v.z = 1.f / (1.f + expf(-v.z));
                    v.w = 1.f / (1.f + expf(-v.w));
                    *(float4*)(&out[act_base + (size_t)(m - M_POSE) * HW + hw]) = v;
                }
            }
        }
    }
#undef LOAD_TILES
#undef STORE_TILES
}

extern "C" void kernel_launch(void* const* d_in, const int* in_sizes, int n_in,
                              void* d_out, int out_size) {
    const float* x  = (const float*)d_in[0];  // [64, 512, 32, 32]
    const float* Wp = (const float*)d_in[1];  // [512, 512]
    const float* bp = (const float*)d_in[2];  // [512]
    const float* Wa = (const float*)d_in[3];  // [32, 512]
    const float* ba = (const float*)d_in[4];  // [32]
    float* out = (float*)d_out;               // poses(33554432) ++ activations(2097152)

    // Pack fused weight/bias into device-global scratch
    {
        int total = M_TOT * A_CH;
        int threads = 256;
        int blocks = (total + threads - 1) / threads;
        pack_weights<<<blocks, threads>>>(Wp, bp, Wa, ba);
    }

    // GEMM: grid (M-tiles=5, HW-tiles=8, images=64)
    {
        dim3 grid((M_TOT + BM - 1) / BM, HW / BN, N_IMG);
        caps_gemm<<<grid, 256>>>(x, out);
    }
}

// round 7
// speedup vs baseline: 3.1194x; 3.1194x over previous
#include <cuda_runtime.h>
#include <cuda_bf16.h>
#include <cstdint>
#include <math.h>

// ---------------- problem constants ----------------
#define N_IMG  64
#define A_CH   512      // K
#define M_POSE 512
#define M_TOT  544
#define M_PAD  640      // 5 x 128 M-tiles
#define HW     1024

// ---------------- tiling ----------------
#define BM 128
#define BN 128
#define BK 32
#define NCH (A_CH / BK)   // 16 K-chunks

// smem per stage: A rows padded to 40 bf16 (80 B), B rows padded to 136 bf16 (272 B)
#define ASTR 40
#define BSTR 136
#define A_TILE_B (BM * ASTR * 2)   // 10240
#define B_TILE_B (BK * BSTR * 2)   // 8704
#define OFF_AHI 0
#define OFF_ALO (A_TILE_B)
#define OFF_BHI (2 * A_TILE_B)
#define OFF_BLO (2 * A_TILE_B + B_TILE_B)
#define STG_B   (2 * A_TILE_B + 2 * B_TILE_B)   // 37888
#define NSTAGE  3
#define SMEM_TOTAL (NSTAGE * STG_B)             // 113664

// ---------------- device-global scratch ----------------
__device__ __nv_bfloat16 g_Whi[M_PAD * A_CH];
__device__ __nv_bfloat16 g_Wlo[M_PAD * A_CH];
__device__ float         g_bias[M_PAD];
__device__ __nv_bfloat16 g_xhi[(size_t)N_IMG * A_CH * HW];  // same layout as x
__device__ __nv_bfloat16 g_xlo[(size_t)N_IMG * A_CH * HW];

// ---------------- PTX helpers ----------------
__device__ __forceinline__ uint32_t s2u(const void* p) {
    uint32_t a;
    asm("{ .reg .u64 t; cvta.to.shared.u64 t, %1; cvt.u32.u64 %0, t; }" : "=r"(a) : "l"(p));
    return a;
}
__device__ __forceinline__ void cp16(uint32_t dst, const void* src) {
    asm volatile("cp.async.cg.shared.global [%0], [%1], 16;\n" :: "r"(dst), "l"(src));
}
#define CP_COMMIT() asm volatile("cp.async.commit_group;\n" ::: "memory")
#define CP_WAIT(n)  asm volatile("cp.async.wait_group %0;\n" :: "n"(n) : "memory")

#define LDSM4(r, addr)                                                        \
    asm volatile("ldmatrix.sync.aligned.m8n8.x4.shared.b16 {%0,%1,%2,%3},[%4];" \
                 : "=r"((r)[0]), "=r"((r)[1]), "=r"((r)[2]), "=r"((r)[3])     \
                 : "r"(addr))
#define LDSM4T(r, addr)                                                       \
    asm volatile("ldmatrix.sync.aligned.m8n8.x4.trans.shared.b16 {%0,%1,%2,%3},[%4];" \
                 : "=r"((r)[0]), "=r"((r)[1]), "=r"((r)[2]), "=r"((r)[3])     \
                 : "r"(addr))
#define MMA_BF16(d, a, b0, b1)                                                \
    asm volatile("mma.sync.aligned.m16n8k16.row.col.f32.bf16.bf16.f32 "       \
                 "{%0,%1,%2,%3},{%4,%5,%6,%7},{%8,%9},{%0,%1,%2,%3};"         \
                 : "+f"((d)[0]), "+f"((d)[1]), "+f"((d)[2]), "+f"((d)[3])     \
                 : "r"((a)[0]), "r"((a)[1]), "r"((a)[2]), "r"((a)[3]),        \
                   "r"(b0), "r"(b1))

// ---------------- prep 1: pack + hi/lo split W, bias ----------------
__global__ void pack_w(const float* __restrict__ Wp, const float* __restrict__ bp,
                       const float* __restrict__ Wa, const float* __restrict__ ba) {
    int i = blockIdx.x * blockDim.x + threadIdx.x;
    if (i < M_PAD * A_CH) {
        int o = i >> 9;
        int a = i & 511;
        float v = 0.f;
        if (o < M_POSE)     v = Wp[o * A_CH + a];
        else if (o < M_TOT) v = Wa[(o - M_POSE) * A_CH + a];
        __nv_bfloat16 h = __float2bfloat16(v);
        g_Whi[i] = h;
        g_Wlo[i] = __float2bfloat16(v - __bfloat162float(h));
    }
    if (i < M_PAD)
        g_bias[i] = (i < M_POSE) ? bp[i] : (i < M_TOT ? ba[i - M_POSE] : 0.f);
}

// ---------------- prep 2: elementwise hi/lo split of x (no transpose) ----------------
__global__ __launch_bounds__(256) void split_x(const float4* __restrict__ x) {
    size_t i = (size_t)blockIdx.x * blockDim.x + threadIdx.x;   // one float4 each
    float4 v = x[i];
    __nv_bfloat16 h0 = __float2bfloat16(v.x), h1 = __float2bfloat16(v.y);
    __nv_bfloat16 h2 = __float2bfloat16(v.z), h3 = __float2bfloat16(v.w);
    __nv_bfloat16 l0 = __float2bfloat16(v.x - __bfloat162float(h0));
    __nv_bfloat16 l1 = __float2bfloat16(v.y - __bfloat162float(h1));
    __nv_bfloat16 l2 = __float2bfloat16(v.z - __bfloat162float(h2));
    __nv_bfloat16 l3 = __float2bfloat16(v.w - __bfloat162float(h3));
    __nv_bfloat162 hA; hA.x = h0; hA.y = h1;
    __nv_bfloat162 hB; hB.x = h2; hB.y = h3;
    __nv_bfloat162 lA; lA.x = l0; lA.y = l1;
    __nv_bfloat162 lB; lB.x = l2; lB.y = l3;
    __nv_bfloat162* ph = reinterpret_cast<__nv_bfloat162*>(&g_xhi[i * 4]);
    __nv_bfloat162* pl = reinterpret_cast<__nv_bfloat162*>(&g_xlo[i * 4]);
    ph[0] = hA; ph[1] = hB;
    pl[0] = lA; pl[1] = lB;
}

// ---------------- main GEMM: mma.sync bf16, 3-term split ----------------
// grid (5, 8, 64), 256 threads (8 warps; warp grid 2M x 4N; warp tile 64x32)
__global__ __launch_bounds__(256, 1) void caps_mma(float* __restrict__ out) {
    extern __shared__ char smem[];
    const uint32_t sb = s2u(smem);
    const int tid  = threadIdx.x;
    const int lane = tid & 31, wid = tid >> 5;
    const int wm = wid & 1, wn = wid >> 1;
    const int m0  = blockIdx.x * BM;
    const int hw0 = blockIdx.y * BN;
    const int img = blockIdx.z;

    const char* whp = (const char*)(g_Whi + (size_t)m0 * A_CH);
    const char* wlp = (const char*)(g_Wlo + (size_t)m0 * A_CH);
    const char* bhp = (const char*)(g_xhi + (size_t)img * A_CH * HW + hw0);
    const char* blp = (const char*)(g_xlo + (size_t)img * A_CH * HW + hw0);

#define ISSUE(stage, ch)                                                        \
    do {                                                                        \
        uint32_t s_ = sb + (stage) * STG_B;                                     \
        size_t kof = (size_t)(ch) * BK;                                         \
        _Pragma("unroll")                                                       \
        for (int j = 0; j < 2; ++j) {                                           \
            int idx = tid + j * 256;                                            \
            int r = idx >> 2, c = idx & 3;                                      \
            uint32_t so = r * (ASTR * 2) + c * 16;                              \
            size_t go = ((size_t)r * A_CH + kof + c * 8) * 2;                   \
            cp16(s_ + OFF_AHI + so, whp + go);                                  \
            cp16(s_ + OFF_ALO + so, wlp + go);                                  \
        }                                                                       \
        _Pragma("unroll")                                                       \
        for (int j = 0; j < 2; ++j) {                                           \
            int idx = tid + j * 256;                                            \
            int r = idx >> 4, c = idx & 15;                                     \
            uint32_t so = r * (BSTR * 2) + c * 16;                              \
            size_t go = ((kof + r) * (size_t)HW + c * 8) * 2;                   \
            cp16(s_ + OFF_BHI + so, bhp + go);                                  \
            cp16(s_ + OFF_BLO + so, blp + go);                                  \
        }                                                                       \
        CP_COMMIT();                                                            \
    } while (0)

    float acc[4][4][4];
#pragma unroll
    for (int i = 0; i < 4; ++i)
#pragma unroll
        for (int j = 0; j < 4; ++j)
#pragma unroll
            for (int k = 0; k < 4; ++k) acc[i][j][k] = 0.f;

    // per-lane ldmatrix address terms
    const uint32_t aLane = (uint32_t)((wm * 64 + (lane & 15)) * (ASTR * 2) + (lane >> 4) * 16);
    const uint32_t bLane = (uint32_t)((lane & 15) * (BSTR * 2) + (wn * 32 + (lane >> 4) * 8) * 2);

    ISSUE(0, 0);
    ISSUE(1, 1);

    for (int ch = 0; ch < NCH; ++ch) {
        if (ch == NCH - 1) CP_WAIT(0); else CP_WAIT(1);
        __syncthreads();
        if (ch + 2 < NCH) ISSUE((ch + 2) % NSTAGE, ch + 2);

        const uint32_t s_ = sb + (ch % NSTAGE) * STG_B;
#pragma unroll
        for (int k16 = 0; k16 < 2; ++k16) {
            uint32_t ah[4][4], al[4][4];
#pragma unroll
            for (int mt = 0; mt < 4; ++mt) {
                uint32_t aAddr = s_ + aLane + mt * 16 * (ASTR * 2) + k16 * 32;
                LDSM4(ah[mt], aAddr + OFF_AHI);
                LDSM4(al[mt], aAddr + OFF_ALO);
            }
            uint32_t bh[8], bl[8];
#pragma unroll
            for (int nt = 0; nt < 2; ++nt) {
                uint32_t bAddr = s_ + bLane + k16 * 16 * (BSTR * 2) + nt * 32;
                LDSM4T(bh + nt * 4, bAddr + OFF_BHI);
                LDSM4T(bl + nt * 4, bAddr + OFF_BLO);
            }
            // pass 0: hi*hi   pass 1: lo*hi   pass 2: hi*lo
            // b-frag for n8 tile j: regs { b[(j>>1)*4 + (j&1)*2], +1 }
#pragma unroll
            for (int mt = 0; mt < 4; ++mt)
#pragma unroll
                for (int j = 0; j < 4; ++j) {
                    int bi = (j >> 1) * 4 + (j & 1) * 2;
                    MMA_BF16(acc[mt][j], ah[mt], bh[bi], bh[bi + 1]);
                }
#pragma unroll
            for (int mt = 0; mt < 4; ++mt)
#pragma unroll
                for (int j = 0; j < 4; ++j) {
                    int bi = (j >> 1) * 4 + (j & 1) * 2;
                    MMA_BF16(acc[mt][j], al[mt], bh[bi], bh[bi + 1]);
                }
#pragma unroll
            for (int mt = 0; mt < 4; ++mt)
#pragma unroll
                for (int j = 0; j < 4; ++j) {
                    int bi = (j >> 1) * 4 + (j & 1) * 2;
                    MMA_BF16(acc[mt][j], ah[mt], bl[bi], bl[bi + 1]);
                }
        }
    }
#undef ISSUE

    // ---- epilogue: bias (+ sigmoid for act rows), write both segments ----
    const int hwBase = hw0 + wn * 32 + (lane & 3) * 2;
#pragma unroll
    for (int mt = 0; mt < 4; ++mt) {
#pragma unroll
        for (int rr = 0; rr < 2; ++rr) {
            const int m = m0 + wm * 64 + mt * 16 + (lane >> 2) + rr * 8;
            if (m >= M_TOT) continue;
            const float bias = g_bias[m];
            const bool is_act = (m >= M_POSE);
            float* rowp;
            if (is_act)
                rowp = out + (size_t)N_IMG * M_POSE * HW
                           + ((size_t)img * (M_TOT - M_POSE) + (m - M_POSE)) * HW;
            else
                rowp = out + ((size_t)img * M_POSE + m) * HW;
#pragma unroll
            for (int j = 0; j < 4; ++j) {
                float2 v;
                v.x = acc[mt][j][rr * 2 + 0] + bias;
                v.y = acc[mt][j][rr * 2 + 1] + bias;
                if (is_act) {
                    v.x = 1.f / (1.f + __expf(-v.x));
                    v.y = 1.f / (1.f + __expf(-v.y));
                }
                *reinterpret_cast<float2*>(rowp + hwBase + j * 8) = v;
            }
        }
    }
}

// ---------------- launch ----------------
extern "C" void kernel_launch(void* const* d_in, const int* in_sizes, int n_in,
                              void* d_out, int out_size) {
    const float* x  = (const float*)d_in[0];  // [64, 512, 32, 32]
    const float* Wp = (const float*)d_in[1];  // [512, 512]
    const float* bp = (const float*)d_in[2];  // [512]
    const float* Wa = (const float*)d_in[3];  // [32, 512]
    const float* ba = (const float*)d_in[4];  // [32]
    float* out = (float*)d_out;

    pack_w<<<(M_PAD * A_CH + 255) / 256, 256>>>(Wp, bp, Wa, ba);

    size_t total4 = (size_t)N_IMG * A_CH * HW / 4;     // 8388608
    split_x<<<(unsigned)(total4 / 256), 256>>>((const float4*)x);

    cudaFuncSetAttribute(caps_mma, cudaFuncAttributeMaxDynamicSharedMemorySize, SMEM_TOTAL);
    caps_mma<<<dim3(M_PAD / BM, HW / BN, N_IMG), 256, SMEM_TOTAL>>>(out);
}

// round 9
// speedup vs baseline: 3.8953x; 1.2487x over previous
#include <cuda_runtime.h>
#include <cuda_bf16.h>
#include <cstdint>
#include <math.h>

// ---------------- problem constants ----------------
#define N_IMG  64
#define A_CH   512      // K
#define M_POSE 512
#define M_TOT  544
#define HW     1024

// ---------------- main GEMM tiling ----------------
#define BM 128
#define BN 256
#define BK 32
#define NCH (A_CH / BK)   // 16

// smem strides (bf16 elems): A rows padded to 40 (80 B = 5x16B, 5 mod 8 = 1? -> conflict-free walk),
// B rows padded to 264 (528 B = 33x16B, 33 mod 8 = 1 -> conflict-free ldmatrix)
#define ASTR 40
#define BSTR 264
#define A_ROW_B (ASTR * 2)      // 80
#define B_ROW_B (BSTR * 2)      // 528
#define A_TILE_B (BM * A_ROW_B) // 10240
#define B_TILE_B (BK * B_ROW_B) // 16896
#define OFF_AHI 0
#define OFF_ALO (A_TILE_B)
#define OFF_BHI (2 * A_TILE_B)
#define OFF_BLO (2 * A_TILE_B + B_TILE_B)
#define STG_B   (2 * A_TILE_B + 2 * B_TILE_B)   // 54272
#define NSTAGE  3
#define SMEM_MAIN (NSTAGE * STG_B)              // 162816

// act kernel smem
#define ACT_M 32
#define A_TILE_ACT (ACT_M * A_ROW_B)            // 2560
#define AOFF_AHI 0
#define AOFF_ALO (A_TILE_ACT)
#define AOFF_BHI (2 * A_TILE_ACT)
#define AOFF_BLO (2 * A_TILE_ACT + B_TILE_B)
#define ASTG_B   (2 * A_TILE_ACT + 2 * B_TILE_B)   // 38912
#define SMEM_ACT (NSTAGE * ASTG_B)                 // 116736

// ---------------- device-global scratch ----------------
__device__ __nv_bfloat16 g_Whi[M_TOT * A_CH];
__device__ __nv_bfloat16 g_Wlo[M_TOT * A_CH];
__device__ float         g_bias[M_TOT];
__device__ __nv_bfloat16 g_xhi[(size_t)N_IMG * A_CH * HW];  // same layout as x
__device__ __nv_bfloat16 g_xlo[(size_t)N_IMG * A_CH * HW];

// ---------------- PTX helpers ----------------
__device__ __forceinline__ uint32_t s2u(const void* p) {
    uint32_t a;
    asm("{ .reg .u64 t; cvta.to.shared.u64 t, %1; cvt.u32.u64 %0, t; }" : "=r"(a) : "l"(p));
    return a;
}
__device__ __forceinline__ void cp16(uint32_t dst, const void* src) {
    asm volatile("cp.async.cg.shared.global [%0], [%1], 16;\n" :: "r"(dst), "l"(src));
}
#define CP_COMMIT() asm volatile("cp.async.commit_group;\n" ::: "memory")
#define CP_WAIT(n)  asm volatile("cp.async.wait_group %0;\n" :: "n"(n) : "memory")

#define LDSM4(r, addr)                                                          \
    asm volatile("ldmatrix.sync.aligned.m8n8.x4.shared.b16 {%0,%1,%2,%3},[%4];" \
                 : "=r"((r)[0]), "=r"((r)[1]), "=r"((r)[2]), "=r"((r)[3])       \
                 : "r"(addr))
#define LDSM4T(r, addr)                                                         \
    asm volatile("ldmatrix.sync.aligned.m8n8.x4.trans.shared.b16 {%0,%1,%2,%3},[%4];" \
                 : "=r"((r)[0]), "=r"((r)[1]), "=r"((r)[2]), "=r"((r)[3])       \
                 : "r"(addr))
#define MMA_BF16(d, a, b0, b1)                                                  \
    asm volatile("mma.sync.aligned.m16n8k16.row.col.f32.bf16.bf16.f32 "         \
                 "{%0,%1,%2,%3},{%4,%5,%6,%7},{%8,%9},{%0,%1,%2,%3};"           \
                 : "+f"((d)[0]), "+f"((d)[1]), "+f"((d)[2]), "+f"((d)[3])       \
                 : "r"((a)[0]), "r"((a)[1]), "r"((a)[2]), "r"((a)[3]),          \
                   "r"(b0), "r"(b1))

// ---------------- prep 1: pack + hi/lo split W, bias ----------------
__global__ void pack_w(const float* __restrict__ Wp, const float* __restrict__ bp,
                       const float* __restrict__ Wa, const float* __restrict__ ba) {
    int i = blockIdx.x * blockDim.x + threadIdx.x;
    if (i < M_TOT * A_CH) {
        int o = i >> 9;
        int a = i & 511;
        float v = (o < M_POSE) ? Wp[o * A_CH + a] : Wa[(o - M_POSE) * A_CH + a];
        __nv_bfloat16 h = __float2bfloat16(v);
        g_Whi[i] = h;
        g_Wlo[i] = __float2bfloat16(v - __bfloat162float(h));
    }
    if (i < M_TOT)
        g_bias[i] = (i < M_POSE) ? bp[i] : ba[i - M_POSE];
}

// ---------------- prep 2: elementwise hi/lo split of x ----------------
__global__ __launch_bounds__(256) void split_x(const float4* __restrict__ x) {
    size_t i = (size_t)blockIdx.x * blockDim.x + threadIdx.x;
    float4 v = x[i];
    __nv_bfloat16 h0 = __float2bfloat16(v.x), h1 = __float2bfloat16(v.y);
    __nv_bfloat16 h2 = __float2bfloat16(v.z), h3 = __float2bfloat16(v.w);
    __nv_bfloat16 l0 = __float2bfloat16(v.x - __bfloat162float(h0));
    __nv_bfloat16 l1 = __float2bfloat16(v.y - __bfloat162float(h1));
    __nv_bfloat16 l2 = __float2bfloat16(v.z - __bfloat162float(h2));
    __nv_bfloat16 l3 = __float2bfloat16(v.w - __bfloat162float(h3));
    __nv_bfloat162 hA; hA.x = h0; hA.y = h1;
    __nv_bfloat162 hB; hB.x = h2; hB.y = h3;
    __nv_bfloat162 lA; lA.x = l0; lA.y = l1;
    __nv_bfloat162 lB; lB.x = l2; lB.y = l3;
    __nv_bfloat162* ph = reinterpret_cast<__nv_bfloat162*>(&g_xhi[i * 4]);
    __nv_bfloat162* pl = reinterpret_cast<__nv_bfloat162*>(&g_xlo[i * 4]);
    ph[0] = hA; ph[1] = hB;
    pl[0] = lA; pl[1] = lB;
}

// ---------------- main GEMM: 512 pose rows, mma.sync bf16 3-term ----------------
// grid (4, 4, 64), 256 threads = 8 warps, warp grid 2M x 4N, warp tile 64x64
__global__ __launch_bounds__(256, 1) void caps_mma(float* __restrict__ out) {
    extern __shared__ char smem[];
    const uint32_t sb = s2u(smem);
    const int tid  = threadIdx.x;
    const int lane = tid & 31, wid = tid >> 5;
    const int wm = wid & 1, wn = wid >> 1;   // wn 0..3
    const int m0  = blockIdx.x * BM;
    const int hw0 = blockIdx.y * BN;
    const int img = blockIdx.z;

    const char* whp = (const char*)(g_Whi + (size_t)m0 * A_CH);
    const char* wlp = (const char*)(g_Wlo + (size_t)m0 * A_CH);
    const char* bhp = (const char*)(g_xhi + (size_t)img * A_CH * HW + hw0);
    const char* blp = (const char*)(g_xlo + (size_t)img * A_CH * HW + hw0);

#define ISSUE(stage, ch)                                                        \
    do {                                                                        \
        uint32_t s_ = sb + (stage) * STG_B;                                     \
        size_t kof = (size_t)(ch) * BK;                                         \
        _Pragma("unroll")                                                       \
        for (int j = 0; j < 2; ++j) {                                           \
            int idx = tid + j * 256;                                            \
            int r = idx >> 2, c = idx & 3;                                      \
            uint32_t so = r * A_ROW_B + c * 16;                                 \
            size_t go = ((size_t)r * A_CH + kof + c * 8) * 2;                   \
            cp16(s_ + OFF_AHI + so, whp + go);                                  \
            cp16(s_ + OFF_ALO + so, wlp + go);                                  \
        }                                                                       \
        _Pragma("unroll")                                                       \
        for (int j = 0; j < 4; ++j) {                                           \
            int idx = tid + j * 256;                                            \
            int r = idx >> 5, c = idx & 31;                                     \
            uint32_t so = r * B_ROW_B + c * 16;                                 \
            size_t go = ((kof + r) * (size_t)HW + c * 8) * 2;                   \
            cp16(s_ + OFF_BHI + so, bhp + go);                                  \
            cp16(s_ + OFF_BLO + so, blp + go);                                  \
        }                                                                       \
        CP_COMMIT();                                                            \
    } while (0)

    float acc[4][8][4];
#pragma unroll
    for (int i = 0; i < 4; ++i)
#pragma unroll
        for (int j = 0; j < 8; ++j)
#pragma unroll
            for (int k = 0; k < 4; ++k) acc[i][j][k] = 0.f;

    const uint32_t aLane = (uint32_t)((wm * 64 + (lane & 15)) * A_ROW_B + (lane >> 4) * 16);
    const uint32_t bLane = (uint32_t)((lane & 15) * B_ROW_B + (wn * 64 + (lane >> 4) * 8) * 2);

    ISSUE(0, 0);
    ISSUE(1, 1);

    for (int ch = 0; ch < NCH; ++ch) {
        if (ch == NCH - 1) CP_WAIT(0); else CP_WAIT(1);
        __syncthreads();
        if (ch + 2 < NCH) ISSUE((ch + 2) % NSTAGE, ch + 2);

        const uint32_t s_ = sb + (ch % NSTAGE) * STG_B;
#pragma unroll
        for (int k16 = 0; k16 < 2; ++k16) {
            uint32_t ah[4][4], al[4][4];
#pragma unroll
            for (int mt = 0; mt < 4; ++mt) {
                uint32_t aAddr = s_ + aLane + mt * 16 * A_ROW_B + k16 * 32;
                LDSM4(ah[mt], aAddr + OFF_AHI);
                LDSM4(al[mt], aAddr + OFF_ALO);
            }
            uint32_t bh[16];
#pragma unroll
            for (int nt = 0; nt < 4; ++nt) {
                uint32_t bAddr = s_ + bLane + k16 * 16 * B_ROW_B + nt * 32;
                LDSM4T(bh + nt * 4, bAddr + OFF_BHI);
            }
            // pass 0: hi*hi
#pragma unroll
            for (int mt = 0; mt < 4; ++mt)
#pragma unroll
                for (int j = 0; j < 8; ++j) {
                    int bi = (j >> 1) * 4 + (j & 1) * 2;
                    MMA_BF16(acc[mt][j], ah[mt], bh[bi], bh[bi + 1]);
                }
            // pass 1: lo(W)*hi(x)
#pragma unroll
            for (int mt = 0; mt < 4; ++mt)
#pragma unroll
                for (int j = 0; j < 8; ++j) {
                    int bi = (j >> 1) * 4 + (j & 1) * 2;
                    MMA_BF16(acc[mt][j], al[mt], bh[bi], bh[bi + 1]);
                }
            // pass 2: hi(W)*lo(x)  (bl loaded late to cap register peak)
            uint32_t bl[16];
#pragma unroll
            for (int nt = 0; nt < 4; ++nt) {
                uint32_t bAddr = s_ + bLane + k16 * 16 * B_ROW_B + nt * 32;
                LDSM4T(bl + nt * 4, bAddr + OFF_BLO);
            }
#pragma unroll
            for (int mt = 0; mt < 4; ++mt)
#pragma unroll
                for (int j = 0; j < 8; ++j) {
                    int bi = (j >> 1) * 4 + (j & 1) * 2;
                    MMA_BF16(acc[mt][j], ah[mt], bl[bi], bl[bi + 1]);
                }
        }
    }
#undef ISSUE

    // ---- epilogue: all rows are pose rows (m < 512), bias only ----
    const int hwBase = hw0 + wn * 64 + (lane & 3) * 2;
#pragma unroll
    for (int mt = 0; mt < 4; ++mt) {
#pragma unroll
        for (int rr = 0; rr < 2; ++rr) {
            const int m = m0 + wm * 64 + mt * 16 + (lane >> 2) + rr * 8;
            const float bias = g_bias[m];
            float* rowp = out + ((size_t)img * M_POSE + m) * HW;
#pragma unroll
            for (int j = 0; j < 8; ++j) {
                float2 v;
                v.x = acc[mt][j][rr * 2 + 0] + bias;
                v.y = acc[mt][j][rr * 2 + 1] + bias;
                *reinterpret_cast<float2*>(rowp + hwBase + j * 8) = v;
            }
        }
    }
}

// ---------------- activation GEMM: 32 rows + sigmoid ----------------
// grid (4, 64), 128 threads = 4 warps, each warp 32(M) x 64(N)
__global__ __launch_bounds__(128, 1) void caps_act(float* __restrict__ out) {
    extern __shared__ char smem[];
    const uint32_t sb = s2u(smem);
    const int tid  = threadIdx.x;
    const int lane = tid & 31, wid = tid >> 5;   // wid = wn 0..3
    const int hw0 = blockIdx.x * BN;
    const int img = blockIdx.y;

    const char* whp = (const char*)(g_Whi + (size_t)M_POSE * A_CH);
    const char* wlp = (const char*)(g_Wlo + (size_t)M_POSE * A_CH);
    const char* bhp = (const char*)(g_xhi + (size_t)img * A_CH * HW + hw0);
    const char* blp = (const char*)(g_xlo + (size_t)img * A_CH * HW + hw0);

#define AISSUE(stage, ch)                                                       \
    do {                                                                        \
        uint32_t s_ = sb + (stage) * ASTG_B;                                    \
        size_t kof = (size_t)(ch) * BK;                                         \
        {                                                                       \
            int r = tid >> 2, c = tid & 3;                                      \
            uint32_t so = r * A_ROW_B + c * 16;                                 \
            size_t go = ((size_t)r * A_CH + kof + c * 8) * 2;                   \
            cp16(s_ + AOFF_AHI + so, whp + go);                                 \
            cp16(s_ + AOFF_ALO + so, wlp + go);                                 \
        }                                                                       \
        _Pragma("unroll")                                                       \
        for (int j = 0; j < 8; ++j) {                                           \
            int idx = tid + j * 128;                                            \
            int r = idx >> 5, c = idx & 31;                                     \
            uint32_t so = r * B_ROW_B + c * 16;                                 \
            size_t go = ((kof + r) * (size_t)HW + c * 8) * 2;                   \
            cp16(s_ + AOFF_BHI + so, bhp + go);                                 \
            cp16(s_ + AOFF_BLO + so, blp + go);                                 \
        }                                                                       \
        CP_COMMIT();                                                            \
    } while (0)

    float acc[2][8][4];
#pragma unroll
    for (int i = 0; i < 2; ++i)
#pragma unroll
        for (int j = 0; j < 8; ++j)
#pragma unroll
            for (int k = 0; k < 4; ++k) acc[i][j][k] = 0.f;

    const uint32_t aLane = (uint32_t)((lane & 15) * A_ROW_B + (lane >> 4) * 16);
    const uint32_t bLane = (uint32_t)((lane & 15) * B_ROW_B + (wid * 64 + (lane >> 4) * 8) * 2);

    AISSUE(0, 0);
    AISSUE(1, 1);

    for (int ch = 0; ch < NCH; ++ch) {
        if (ch == NCH - 1) CP_WAIT(0); else CP_WAIT(1);
        __syncthreads();
        if (ch + 2 < NCH) AISSUE((ch + 2) % NSTAGE, ch + 2);

        const uint32_t s_ = sb + (ch % NSTAGE) * ASTG_B;
#pragma unroll
        for (int k16 = 0; k16 < 2; ++k16) {
            uint32_t ah[2][4], al[2][4];
#pragma unroll
            for (int mt = 0; mt < 2; ++mt) {
                uint32_t aAddr = s_ + aLane + mt * 16 * A_ROW_B + k16 * 32;
                LDSM4(ah[mt], aAddr + AOFF_AHI);
                LDSM4(al[mt], aAddr + AOFF_ALO);
            }
            uint32_t bh[16], bl[16];
#pragma unroll
            for (int nt = 0; nt < 4; ++nt) {
                uint32_t bAddr = s_ + bLane + k16 * 16 * B_ROW_B + nt * 32;
                LDSM4T(bh + nt * 4, bAddr + AOFF_BHI);
                LDSM4T(bl + nt * 4, bAddr + AOFF_BLO);
            }
#pragma unroll
            for (int mt = 0; mt < 2; ++mt)
#pragma unroll
                for (int j = 0; j < 8; ++j) {
                    int bi = (j >> 1) * 4 + (j & 1) * 2;
                    MMA_BF16(acc[mt][j], ah[mt], bh[bi], bh[bi + 1]);
                    MMA_BF16(acc[mt][j], al[mt], bh[bi], bh[bi + 1]);
                    MMA_BF16(acc[mt][j], ah[mt], bl[bi], bl[bi + 1]);
                }
        }
    }
#undef AISSUE

    // ---- epilogue: sigmoid rows, activation output segment ----
    const int hwBase = hw0 + wid * 64 + (lane & 3) * 2;
    float* actout = out + (size_t)N_IMG * M_POSE * HW;
#pragma unroll
    for (int mt = 0; mt < 2; ++mt) {
#pragma unroll
        for (int rr = 0; rr < 2; ++rr) {
            const int m = mt * 16 + (lane >> 2) + rr * 8;   // 0..31
            const float bias = g_bias[M_POSE + m];
            float* rowp = actout + ((size_t)img * (M_TOT - M_POSE) + m) * HW;
#pragma unroll
            for (int j = 0; j < 8; ++j) {
                float2 v;
                v.x = acc[mt][j][rr * 2 + 0] + bias;
                v.y = acc[mt][j][rr * 2 + 1] + bias;
                v.x = 1.f / (1.f + __expf(-v.x));
                v.y = 1.f / (1.f + __expf(-v.y));
                *reinterpret_cast<float2*>(rowp + hwBase + j * 8) = v;
            }
        }
    }
}

// ---------------- launch ----------------
extern "C" void kernel_launch(void* const* d_in, const int* in_sizes, int n_in,
                              void* d_out, int out_size) {
    const float* x  = (const float*)d_in[0];  // [64, 512, 32, 32]
    const float* Wp = (const float*)d_in[1];  // [512, 512]
    const float* bp = (const float*)d_in[2];  // [512]
    const float* Wa = (const float*)d_in[3];  // [32, 512]
    const float* ba = (const float*)d_in[4];  // [32]
    float* out = (float*)d_out;

    pack_w<<<(M_TOT * A_CH + 255) / 256, 256>>>(Wp, bp, Wa, ba);

    size_t total4 = (size_t)N_IMG * A_CH * HW / 4;
    split_x<<<(unsigned)(total4 / 256), 256>>>((const float4*)x);

    cudaFuncSetAttribute(caps_mma, cudaFuncAttributeMaxDynamicSharedMemorySize, SMEM_MAIN);
    cudaFuncSetAttribute(caps_act, cudaFuncAttributeMaxDynamicSharedMemorySize, SMEM_ACT);

    caps_mma<<<dim3(BM == 128 ? M_POSE / BM : 4, HW / BN, N_IMG), 256, SMEM_MAIN>>>(out);
    caps_act<<<dim3(HW / BN, N_IMG), 128, SMEM_ACT>>>(out);
}

// round 10
// speedup vs baseline: 3.9392x; 1.0113x over previous
#include <cuda_runtime.h>
#include <cuda_bf16.h>
#include <cstdint>
#include <math.h>

// ---------------- problem constants ----------------
#define N_IMG  64
#define A_CH   512      // K
#define M_POSE 512
#define M_TOT  544
#define HW     1024

// ---------------- GEMM tiling ----------------
#define BM 128
#define BN 256
#define BK 32
#define NCH (A_CH / BK)   // 16

// smem strides (bf16 elems): A rows padded to 40 (80 B), B rows padded to 264 (528 B)
#define ASTR 40
#define BSTR 264
#define A_ROW_B (ASTR * 2)      // 80
#define B_ROW_B (BSTR * 2)      // 528
#define A_TILE_B (BM * A_ROW_B) // 10240
#define B_TILE_B (BK * B_ROW_B) // 16896
#define OFF_AHI 0
#define OFF_ALO (A_TILE_B)
#define OFF_BHI (2 * A_TILE_B)
#define OFF_BLO (2 * A_TILE_B + B_TILE_B)
#define STG_B   (2 * A_TILE_B + 2 * B_TILE_B)   // 54272
#define NSTAGE  3
#define SMEM_MAIN (NSTAGE * STG_B)              // 162816

// ---------------- device-global scratch ----------------
__device__ __nv_bfloat16 g_Whi[M_TOT * A_CH];
__device__ __nv_bfloat16 g_Wlo[M_TOT * A_CH];
__device__ float         g_bias[M_TOT];
__device__ __nv_bfloat16 g_xhi[(size_t)N_IMG * A_CH * HW];  // same layout as x
__device__ __nv_bfloat16 g_xlo[(size_t)N_IMG * A_CH * HW];

// ---------------- PTX helpers ----------------
__device__ __forceinline__ uint32_t s2u(const void* p) {
    uint32_t a;
    asm("{ .reg .u64 t; cvta.to.shared.u64 t, %1; cvt.u32.u64 %0, t; }" : "=r"(a) : "l"(p));
    return a;
}
__device__ __forceinline__ void cp16(uint32_t dst, const void* src) {
    asm volatile("cp.async.cg.shared.global [%0], [%1], 16;\n" :: "r"(dst), "l"(src));
}
#define CP_COMMIT() asm volatile("cp.async.commit_group;\n" ::: "memory")
#define CP_WAIT(n)  asm volatile("cp.async.wait_group %0;\n" :: "n"(n) : "memory")

#define LDSM4(r, addr)                                                          \
    asm volatile("ldmatrix.sync.aligned.m8n8.x4.shared.b16 {%0,%1,%2,%3},[%4];" \
                 : "=r"((r)[0]), "=r"((r)[1]), "=r"((r)[2]), "=r"((r)[3])       \
                 : "r"(addr))
#define LDSM4T(r, addr)                                                         \
    asm volatile("ldmatrix.sync.aligned.m8n8.x4.trans.shared.b16 {%0,%1,%2,%3},[%4];" \
                 : "=r"((r)[0]), "=r"((r)[1]), "=r"((r)[2]), "=r"((r)[3])       \
                 : "r"(addr))
#define MMA_BF16(d, a, b0, b1)                                                  \
    asm volatile("mma.sync.aligned.m16n8k16.row.col.f32.bf16.bf16.f32 "         \
                 "{%0,%1,%2,%3},{%4,%5,%6,%7},{%8,%9},{%0,%1,%2,%3};"           \
                 : "+f"((d)[0]), "+f"((d)[1]), "+f"((d)[2]), "+f"((d)[3])       \
                 : "r"((a)[0]), "r"((a)[1]), "r"((a)[2]), "r"((a)[3]),          \
                   "r"(b0), "r"(b1))

// ---------------- prep 1: pack + hi/lo split W, bias ----------------
__global__ void pack_w(const float* __restrict__ Wp, const float* __restrict__ bp,
                       const float* __restrict__ Wa, const float* __restrict__ ba) {
    int i = blockIdx.x * blockDim.x + threadIdx.x;
    if (i < M_TOT * A_CH) {
        int o = i >> 9;
        int a = i & 511;
        float v = (o < M_POSE) ? Wp[o * A_CH + a] : Wa[(o - M_POSE) * A_CH + a];
        __nv_bfloat16 h = __float2bfloat16(v);
        g_Whi[i] = h;
        g_Wlo[i] = __float2bfloat16(v - __bfloat162float(h));
    }
    if (i < M_TOT)
        g_bias[i] = (i < M_POSE) ? bp[i] : ba[i - M_POSE];
}

// ---------------- prep 2: elementwise hi/lo split of x (8 floats/thread) ----------------
__global__ __launch_bounds__(256) void split_x(const float4* __restrict__ x) {
    size_t i = ((size_t)blockIdx.x * blockDim.x + threadIdx.x) * 2;
    uint4 ho[2], lo[2];
#pragma unroll
    for (int q = 0; q < 2; ++q) {
        float4 v = x[i + q];
        __nv_bfloat16 h0 = __float2bfloat16(v.x), h1 = __float2bfloat16(v.y);
        __nv_bfloat16 h2 = __float2bfloat16(v.z), h3 = __float2bfloat16(v.w);
        __nv_bfloat16 l0 = __float2bfloat16(v.x - __bfloat162float(h0));
        __nv_bfloat16 l1 = __float2bfloat16(v.y - __bfloat162float(h1));
        __nv_bfloat16 l2 = __float2bfloat16(v.z - __bfloat162float(h2));
        __nv_bfloat16 l3 = __float2bfloat16(v.w - __bfloat162float(h3));
        __nv_bfloat162 a; a.x = h0; a.y = h1;
        __nv_bfloat162 b; b.x = h2; b.y = h3;
        __nv_bfloat162 c; c.x = l0; c.y = l1;
        __nv_bfloat162 d; d.x = l2; d.y = l3;
        ((uint32_t*)&ho[0])[q * 2 + 0] = *reinterpret_cast<uint32_t*>(&a);
        ((uint32_t*)&ho[0])[q * 2 + 1] = *reinterpret_cast<uint32_t*>(&b);
        ((uint32_t*)&lo[0])[q * 2 + 0] = *reinterpret_cast<uint32_t*>(&c);
        ((uint32_t*)&lo[0])[q * 2 + 1] = *reinterpret_cast<uint32_t*>(&d);
    }
    *reinterpret_cast<uint4*>(&g_xhi[i * 4]) = ho[0];
    *reinterpret_cast<uint4*>(&g_xlo[i * 4]) = lo[0];
}

// ---------------- fused GEMM: pose tiles (bx<4) + act tile (bx==4) ----------------
// grid (5, 4, 64), 256 threads = 8 warps
__global__ __launch_bounds__(256, 1) void caps_mma(float* __restrict__ out) {
    extern __shared__ char smem[];
    const uint32_t sb = s2u(smem);
    const int tid  = threadIdx.x;
    const int lane = tid & 31, wid = tid >> 5;
    const int hw0 = blockIdx.y * BN;
    const int img = blockIdx.z;
    const bool is_act_cta = (blockIdx.x == 4);
    const int m0 = is_act_cta ? M_POSE : blockIdx.x * BM;

    const char* whp = (const char*)(g_Whi + (size_t)m0 * A_CH);
    const char* wlp = (const char*)(g_Wlo + (size_t)m0 * A_CH);
    const char* bhp = (const char*)(g_xhi + (size_t)img * A_CH * HW + hw0);
    const char* blp = (const char*)(g_xlo + (size_t)img * A_CH * HW + hw0);

    // B-tile loader shared by both branches
#define ISSUE_B(s_, kof)                                                        \
    do {                                                                        \
        _Pragma("unroll")                                                       \
        for (int j = 0; j < 4; ++j) {                                           \
            int idx = tid + j * 256;                                            \
            int r = idx >> 5, c = idx & 31;                                     \
            uint32_t so = r * B_ROW_B + c * 16;                                 \
            size_t go = ((kof + r) * (size_t)HW + c * 8) * 2;                   \
            cp16((s_) + OFF_BHI + so, bhp + go);                                \
            cp16((s_) + OFF_BLO + so, blp + go);                                \
        }                                                                       \
    } while (0)

    if (!is_act_cta) {
        // ======================= pose branch: 128 x 256 =======================
        const int wm = wid & 1, wn = wid >> 1;

#define ISSUE(stage, ch)                                                        \
    do {                                                                        \
        uint32_t s_ = sb + (stage) * STG_B;                                     \
        size_t kof = (size_t)(ch) * BK;                                         \
        _Pragma("unroll")                                                       \
        for (int j = 0; j < 2; ++j) {                                           \
            int idx = tid + j * 256;                                            \
            int r = idx >> 2, c = idx & 3;                                      \
            uint32_t so = r * A_ROW_B + c * 16;                                 \
            size_t go = ((size_t)r * A_CH + kof + c * 8) * 2;                   \
            cp16(s_ + OFF_AHI + so, whp + go);                                  \
            cp16(s_ + OFF_ALO + so, wlp + go);                                  \
        }                                                                       \
        ISSUE_B(s_, kof);                                                       \
        CP_COMMIT();                                                            \
    } while (0)

        float acc[4][8][4];
#pragma unroll
        for (int i = 0; i < 4; ++i)
#pragma unroll
            for (int j = 0; j < 8; ++j)
#pragma unroll
                for (int k = 0; k < 4; ++k) acc[i][j][k] = 0.f;

        const uint32_t aLane = (uint32_t)((wm * 64 + (lane & 15)) * A_ROW_B + (lane >> 4) * 16);
        const uint32_t bLane = (uint32_t)((lane & 15) * B_ROW_B + (wn * 64 + (lane >> 4) * 8) * 2);

        ISSUE(0, 0);
        ISSUE(1, 1);

        for (int ch = 0; ch < NCH; ++ch) {
            if (ch == NCH - 1) CP_WAIT(0); else CP_WAIT(1);
            __syncthreads();
            if (ch + 2 < NCH) ISSUE((ch + 2) % NSTAGE, ch + 2);

            const uint32_t s_ = sb + (ch % NSTAGE) * STG_B;
#pragma unroll
            for (int k16 = 0; k16 < 2; ++k16) {
                uint32_t ah[4][4], al[4][4];
#pragma unroll
                for (int mt = 0; mt < 4; ++mt) {
                    uint32_t aAddr = s_ + aLane + mt * 16 * A_ROW_B + k16 * 32;
                    LDSM4(ah[mt], aAddr + OFF_AHI);
                    LDSM4(al[mt], aAddr + OFF_ALO);
                }
                uint32_t bh[16];
#pragma unroll
                for (int nt = 0; nt < 4; ++nt) {
                    uint32_t bAddr = s_ + bLane + k16 * 16 * B_ROW_B + nt * 32;
                    LDSM4T(bh + nt * 4, bAddr + OFF_BHI);
                }
#pragma unroll
                for (int mt = 0; mt < 4; ++mt)
#pragma unroll
                    for (int j = 0; j < 8; ++j) {
                        int bi = (j >> 1) * 4 + (j & 1) * 2;
                        MMA_BF16(acc[mt][j], ah[mt], bh[bi], bh[bi + 1]);
                    }
#pragma unroll
                for (int mt = 0; mt < 4; ++mt)
#pragma unroll
                    for (int j = 0; j < 8; ++j) {
                        int bi = (j >> 1) * 4 + (j & 1) * 2;
                        MMA_BF16(acc[mt][j], al[mt], bh[bi], bh[bi + 1]);
                    }
                uint32_t bl[16];
#pragma unroll
                for (int nt = 0; nt < 4; ++nt) {
                    uint32_t bAddr = s_ + bLane + k16 * 16 * B_ROW_B + nt * 32;
                    LDSM4T(bl + nt * 4, bAddr + OFF_BLO);
                }
#pragma unroll
                for (int mt = 0; mt < 4; ++mt)
#pragma unroll
                    for (int j = 0; j < 8; ++j) {
                        int bi = (j >> 1) * 4 + (j & 1) * 2;
                        MMA_BF16(acc[mt][j], ah[mt], bl[bi], bl[bi + 1]);
                    }
            }
        }
#undef ISSUE

        const int hwBase = hw0 + wn * 64 + (lane & 3) * 2;
#pragma unroll
        for (int mt = 0; mt < 4; ++mt) {
#pragma unroll
            for (int rr = 0; rr < 2; ++rr) {
                const int m = m0 + wm * 64 + mt * 16 + (lane >> 2) + rr * 8;
                const float bias = g_bias[m];
                float* rowp = out + ((size_t)img * M_POSE + m) * HW;
#pragma unroll
                for (int j = 0; j < 8; ++j) {
                    float2 v;
                    v.x = acc[mt][j][rr * 2 + 0] + bias;
                    v.y = acc[mt][j][rr * 2 + 1] + bias;
                    *reinterpret_cast<float2*>(rowp + hwBase + j * 8) = v;
                }
            }
        }
    } else {
        // ======================= act branch: 32 x 256 + sigmoid =======================
        // 8 warps side by side in N: warp tile 32(M) x 32(N)
#define AISSUE(stage, ch)                                                       \
    do {                                                                        \
        uint32_t s_ = sb + (stage) * STG_B;                                     \
        size_t kof = (size_t)(ch) * BK;                                         \
        if (tid < 128) {                                                        \
            int r = tid >> 2, c = tid & 3;                                      \
            uint32_t so = r * A_ROW_B + c * 16;                                 \
            size_t go = ((size_t)r * A_CH + kof + c * 8) * 2;                   \
            cp16(s_ + OFF_AHI + so, whp + go);                                  \
            cp16(s_ + OFF_ALO + so, wlp + go);                                  \
        }                                                                       \
        ISSUE_B(s_, kof);                                                       \
        CP_COMMIT();                                                            \
    } while (0)

        float acc[2][4][4];
#pragma unroll
        for (int i = 0; i < 2; ++i)
#pragma unroll
            for (int j = 0; j < 4; ++j)
#pragma unroll
                for (int k = 0; k < 4; ++k) acc[i][j][k] = 0.f;

        const uint32_t aLane = (uint32_t)((lane & 15) * A_ROW_B + (lane >> 4) * 16);
        const uint32_t bLane = (uint32_t)((lane & 15) * B_ROW_B + (wid * 32 + (lane >> 4) * 8) * 2);

        AISSUE(0, 0);
        AISSUE(1, 1);

        for (int ch = 0; ch < NCH; ++ch) {
            if (ch == NCH - 1) CP_WAIT(0); else CP_WAIT(1);
            __syncthreads();
            if (ch + 2 < NCH) AISSUE((ch + 2) % NSTAGE, ch + 2);

            const uint32_t s_ = sb + (ch % NSTAGE) * STG_B;
#pragma unroll
            for (int k16 = 0; k16 < 2; ++k16) {
                uint32_t ah[2][4], al[2][4];
#pragma unroll
                for (int mt = 0; mt < 2; ++mt) {
                    uint32_t aAddr = s_ + aLane + mt * 16 * A_ROW_B + k16 * 32;
                    LDSM4(ah[mt], aAddr + OFF_AHI);
                    LDSM4(al[mt], aAddr + OFF_ALO);
                }
                uint32_t bh[8], bl[8];
#pragma unroll
                for (int nt = 0; nt < 2; ++nt) {
                    uint32_t bAddr = s_ + bLane + k16 * 16 * B_ROW_B + nt * 32;
                    LDSM4T(bh + nt * 4, bAddr + OFF_BHI);
                    LDSM4T(bl + nt * 4, bAddr + OFF_BLO);
                }
#pragma unroll
                for (int mt = 0; mt < 2; ++mt)
#pragma unroll
                    for (int j = 0; j < 4; ++j) {
                        int bi = (j >> 1) * 4 + (j & 1) * 2;
                        MMA_BF16(acc[mt][j], ah[mt], bh[bi], bh[bi + 1]);
                        MMA_BF16(acc[mt][j], al[mt], bh[bi], bh[bi + 1]);
                        MMA_BF16(acc[mt][j], ah[mt], bl[bi], bl[bi + 1]);
                    }
            }
        }
#undef AISSUE

        const int hwBase = hw0 + wid * 32 + (lane & 3) * 2;
        float* actout = out + (size_t)N_IMG * M_POSE * HW;
#pragma unroll
        for (int mt = 0; mt < 2; ++mt) {
#pragma unroll
            for (int rr = 0; rr < 2; ++rr) {
                const int m = mt * 16 + (lane >> 2) + rr * 8;   // 0..31
                const float bias = g_bias[M_POSE + m];
                float* rowp = actout + ((size_t)img * (M_TOT - M_POSE) + m) * HW;
#pragma unroll
                for (int j = 0; j < 4; ++j) {
                    float2 v;
                    v.x = acc[mt][j][rr * 2 + 0] + bias;
                    v.y = acc[mt][j][rr * 2 + 1] + bias;
                    v.x = 1.f / (1.f + __expf(-v.x));
                    v.y = 1.f / (1.f + __expf(-v.y));
                    *reinterpret_cast<float2*>(rowp + hwBase + j * 8) = v;
                }
            }
        }
    }
#undef ISSUE_B
}

// ---------------- launch ----------------
extern "C" void kernel_launch(void* const* d_in, const int* in_sizes, int n_in,
                              void* d_out, int out_size) {
    const float* x  = (const float*)d_in[0];  // [64, 512, 32, 32]
    const float* Wp = (const float*)d_in[1];  // [512, 512]
    const float* bp = (const float*)d_in[2];  // [512]
    const float* Wa = (const float*)d_in[3];  // [32, 512]
    const float* ba = (const float*)d_in[4];  // [32]
    float* out = (float*)d_out;

    pack_w<<<(M_TOT * A_CH + 255) / 256, 256>>>(Wp, bp, Wa, ba);

    size_t total4 = (size_t)N_IMG * A_CH * HW / 4;   // float4 count
    split_x<<<(unsigned)(total4 / 512), 256>>>((const float4*)x);

    cudaFuncSetAttribute(caps_mma, cudaFuncAttributeMaxDynamicSharedMemorySize, SMEM_MAIN);
    caps_mma<<<dim3(5, HW / BN, N_IMG), 256, SMEM_MAIN>>>(out);
}

// round 11
// speedup vs baseline: 5.4570x; 1.3853x over previous
#include <cuda_runtime.h>
#include <cuda_bf16.h>
#include <cstdint>
#include <math.h>

// ---------------- problem constants ----------------
#define N_IMG  64
#define A_CH   512      // K
#define M_POSE 512
#define M_TOT  544
#define HW     1024

// ---------------- GEMM tiling ----------------
#define BM 128
#define BN 256
#define BK 32
#define NCH (A_CH / BK)   // 16

// smem (fp32/tf32 data):
// A tile: 128 rows x 32 floats, row stride 36 floats (144 B, 16B-aligned, conflict-free ldmatrix)
// B tile: 32 rows x 256 floats, row stride 264 floats (1056 B; 264 mod 32 = 8 -> conflict-free frag LDS)
#define ASTRF 36
#define BSTRF 264
#define A_ROW_B (ASTRF * 4)       // 144
#define B_ROW_B (BSTRF * 4)       // 1056
#define A_TILE_B (BM * A_ROW_B)   // 18432
#define B_TILE_B (BK * B_ROW_B)   // 33792
#define OFF_A 0
#define OFF_B (A_TILE_B)
#define STG_B (A_TILE_B + B_TILE_B)   // 52224
#define NSTAGE 3
#define SMEM_MAIN (NSTAGE * STG_B)    // 156672

// ---------------- device-global scratch ----------------
__device__ float g_W[M_TOT * A_CH];   // tf32-rounded fp32 (low mantissa bits zero)
__device__ float g_bias[M_TOT];

// ---------------- PTX helpers ----------------
__device__ __forceinline__ uint32_t s2u(const void* p) {
    uint32_t a;
    asm("{ .reg .u64 t; cvta.to.shared.u64 t, %1; cvt.u32.u64 %0, t; }" : "=r"(a) : "l"(p));
    return a;
}
__device__ __forceinline__ void cp16(uint32_t dst, const void* src) {
    asm volatile("cp.async.cg.shared.global [%0], [%1], 16;\n" :: "r"(dst), "l"(src));
}
#define CP_COMMIT() asm volatile("cp.async.commit_group;\n" ::: "memory")
#define CP_WAIT(n)  asm volatile("cp.async.wait_group %0;\n" :: "n"(n) : "memory")

// ldmatrix.b16 used to fetch 32-bit tf32 words (each "b16 pair" = one tf32 word)
#define LDSM4(r, addr)                                                          \
    asm volatile("ldmatrix.sync.aligned.m8n8.x4.shared.b16 {%0,%1,%2,%3},[%4];" \
                 : "=r"((r)[0]), "=r"((r)[1]), "=r"((r)[2]), "=r"((r)[3])       \
                 : "r"(addr))

#define MMA_TF32(d, a, b0, b1)                                                  \
    asm volatile("mma.sync.aligned.m16n8k8.row.col.f32.tf32.tf32.f32 "          \
                 "{%0,%1,%2,%3},{%4,%5,%6,%7},{%8,%9},{%0,%1,%2,%3};"           \
                 : "+f"((d)[0]), "+f"((d)[1]), "+f"((d)[2]), "+f"((d)[3])       \
                 : "r"((a)[0]), "r"((a)[1]), "r"((a)[2]), "r"((a)[3]),          \
                   "r"(b0), "r"(b1))

__device__ __forceinline__ uint32_t f2tf32(float f) {
    uint32_t r;
    asm("cvt.rna.tf32.f32 %0, %1;" : "=r"(r) : "f"(f));
    return r;
}
__device__ __forceinline__ uint32_t lds32(uint32_t addr) {
    uint32_t v;
    asm volatile("ld.shared.b32 %0, [%1];" : "=r"(v) : "r"(addr));
    return v;
}

// ---------------- prep: pack W (pose ++ act) with tf32 pre-rounding, bias ----------------
__global__ void pack_w(const float* __restrict__ Wp, const float* __restrict__ bp,
                       const float* __restrict__ Wa, const float* __restrict__ ba) {
    int i = blockIdx.x * blockDim.x + threadIdx.x;
    if (i < M_TOT * A_CH) {
        int o = i >> 9;
        int a = i & 511;
        float v = (o < M_POSE) ? Wp[o * A_CH + a] : Wa[(o - M_POSE) * A_CH + a];
        g_W[i] = __uint_as_float(f2tf32(v));   // canonical tf32 bits -> no cvt in mainloop
    }
    if (i < M_TOT)
        g_bias[i] = (i < M_POSE) ? bp[i] : ba[i - M_POSE];
}

// ---------------- fused GEMM: pose tiles (bx<4) + act tile (bx==4), tf32 single pass ----------------
// grid (5, 4, 64), 256 threads = 8 warps
__global__ __launch_bounds__(256, 1) void caps_mma(const float* __restrict__ x,
                                                   float* __restrict__ out) {
    extern __shared__ char smem[];
    const uint32_t sb = s2u(smem);
    const int tid  = threadIdx.x;
    const int lane = tid & 31, wid = tid >> 5;
    const int hw0 = blockIdx.y * BN;
    const int img = blockIdx.z;
    const bool is_act_cta = (blockIdx.x == 4);
    const int m0 = is_act_cta ? M_POSE : blockIdx.x * BM;

    const char* wptr = (const char*)(g_W + (size_t)m0 * A_CH);
    const char* xptr = (const char*)(x + (size_t)img * A_CH * HW + hw0);

    // B-tile loader (32 rows x 1024 B), 8 cp16/thread
#define ISSUE_B(s_, kof)                                                        \
    do {                                                                        \
        _Pragma("unroll")                                                       \
        for (int j = 0; j < 8; ++j) {                                           \
            int idx = tid + j * 256;                                            \
            int r = idx >> 6, c = idx & 63;                                     \
            uint32_t so = r * B_ROW_B + c * 16;                                 \
            size_t go = (((kof) + r) * (size_t)HW + c * 4) * 4;                 \
            cp16((s_) + OFF_B + so, xptr + go);                                 \
        }                                                                       \
    } while (0)

    // ldmatrix lane address (quadrant layout for tf32 m16k8 A fragment)
    const uint32_t aQuad = (uint32_t)(((lane & 7) + ((lane >> 3) & 1) * 8) * A_ROW_B
                                      + ((lane >> 4) & 1) * 16);

    if (!is_act_cta) {
        // ======================= pose branch: 128 x 256 =======================
        const int wm = wid & 1, wn = wid >> 1;

#define ISSUE(stage, ch)                                                        \
    do {                                                                        \
        uint32_t s_ = sb + (stage) * STG_B;                                     \
        size_t kof = (size_t)(ch) * BK;                                         \
        _Pragma("unroll")                                                       \
        for (int j = 0; j < 4; ++j) {                                           \
            int idx = tid + j * 256;                                            \
            int r = idx >> 3, c = idx & 7;                                      \
            uint32_t so = r * A_ROW_B + c * 16;                                 \
            size_t go = ((size_t)r * A_CH + kof + c * 4) * 4;                   \
            cp16(s_ + OFF_A + so, wptr + go);                                   \
        }                                                                       \
        ISSUE_B(s_, kof);                                                       \
        CP_COMMIT();                                                            \
    } while (0)

        float acc[4][8][4];
#pragma unroll
        for (int i = 0; i < 4; ++i)
#pragma unroll
            for (int j = 0; j < 8; ++j)
#pragma unroll
                for (int k = 0; k < 4; ++k) acc[i][j][k] = 0.f;

        const uint32_t aLane = (uint32_t)(wm * 64 * A_ROW_B) + aQuad;
        // B frag base: word (k)*(BSTRF) + n ; lane part: k=lane&3, n=lane>>2
        const uint32_t bLane = (uint32_t)(((lane & 3) * BSTRF + wn * 64 + (lane >> 2)) * 4);

        ISSUE(0, 0);
        ISSUE(1, 1);

        for (int ch = 0; ch < NCH; ++ch) {
            if (ch == NCH - 1) CP_WAIT(0); else CP_WAIT(1);
            __syncthreads();
            if (ch + 2 < NCH) ISSUE((ch + 2) % NSTAGE, ch + 2);

            const uint32_t s_ = sb + (ch % NSTAGE) * STG_B;
#pragma unroll
            for (int k8 = 0; k8 < 4; ++k8) {
                // B fragments: 8 n-tiles x 2 regs, scalar LDS + cvt to tf32
                uint32_t bf[8][2];
                const uint32_t bb = s_ + OFF_B + bLane + k8 * 8 * B_ROW_B;
#pragma unroll
                for (int nt = 0; nt < 8; ++nt) {
                    bf[nt][0] = f2tf32(__uint_as_float(lds32(bb + nt * 32)));
                    bf[nt][1] = f2tf32(__uint_as_float(lds32(bb + nt * 32 + 4 * B_ROW_B)));
                }
                // A fragments: 4 m16 tiles via ldmatrix (already tf32 bits)
                uint32_t af[4][4];
#pragma unroll
                for (int mt = 0; mt < 4; ++mt) {
                    uint32_t aAddr = s_ + OFF_A + aLane + mt * 16 * A_ROW_B + k8 * 32;
                    LDSM4(af[mt], aAddr);
                }
#pragma unroll
                for (int mt = 0; mt < 4; ++mt)
#pragma unroll
                    for (int j = 0; j < 8; ++j)
                        MMA_TF32(acc[mt][j], af[mt], bf[j][0], bf[j][1]);
            }
        }
#undef ISSUE

        const int hwBase = hw0 + wn * 64 + (lane & 3) * 2;
#pragma unroll
        for (int mt = 0; mt < 4; ++mt) {
#pragma unroll
            for (int rr = 0; rr < 2; ++rr) {
                const int m = m0 + wm * 64 + mt * 16 + (lane >> 2) + rr * 8;
                const float bias = g_bias[m];
                float* rowp = out + ((size_t)img * M_POSE + m) * HW;
#pragma unroll
                for (int j = 0; j < 8; ++j) {
                    float2 v;
                    v.x = acc[mt][j][rr * 2 + 0] + bias;
                    v.y = acc[mt][j][rr * 2 + 1] + bias;
                    *reinterpret_cast<float2*>(rowp + hwBase + j * 8) = v;
                }
            }
        }
    } else {
        // ======================= act branch: 32 x 256 + sigmoid =======================
        // 8 warps side by side in N: warp tile 32(M) x 32(N)
#define AISSUE(stage, ch)                                                       \
    do {                                                                        \
        uint32_t s_ = sb + (stage) * STG_B;                                     \
        size_t kof = (size_t)(ch) * BK;                                         \
        {                                                                       \
            int r = tid >> 3, c = tid & 7;                                      \
            uint32_t so = r * A_ROW_B + c * 16;                                 \
            size_t go = ((size_t)r * A_CH + kof + c * 4) * 4;                   \
            cp16(s_ + OFF_A + so, wptr + go);                                   \
        }                                                                       \
        ISSUE_B(s_, kof);                                                       \
        CP_COMMIT();                                                            \
    } while (0)

        float acc[2][4][4];
#pragma unroll
        for (int i = 0; i < 2; ++i)
#pragma unroll
            for (int j = 0; j < 4; ++j)
#pragma unroll
                for (int k = 0; k < 4; ++k) acc[i][j][k] = 0.f;

        const uint32_t aLane = aQuad;
        const uint32_t bLane = (uint32_t)(((lane & 3) * BSTRF + wid * 32 + (lane >> 2)) * 4);

        AISSUE(0, 0);
        AISSUE(1, 1);

        for (int ch = 0; ch < NCH; ++ch) {
            if (ch == NCH - 1) CP_WAIT(0); else CP_WAIT(1);
            __syncthreads();
            if (ch + 2 < NCH) AISSUE((ch + 2) % NSTAGE, ch + 2);

            const uint32_t s_ = sb + (ch % NSTAGE) * STG_B;
#pragma unroll
            for (int k8 = 0; k8 < 4; ++k8) {
                uint32_t bf[4][2];
                const uint32_t bb = s_ + OFF_B + bLane + k8 * 8 * B_ROW_B;
#pragma unroll
                for (int nt = 0; nt < 4; ++nt) {
                    bf[nt][0] = f2tf32(__uint_as_float(lds32(bb + nt * 32)));
                    bf[nt][1] = f2tf32(__uint_as_float(lds32(bb + nt * 32 + 4 * B_ROW_B)));
                }
                uint32_t af[2][4];
#pragma unroll
                for (int mt = 0; mt < 2; ++mt) {
                    uint32_t aAddr = s_ + OFF_A + aLane + mt * 16 * A_ROW_B + k8 * 32;
                    LDSM4(af[mt], aAddr);
                }
#pragma unroll
                for (int mt = 0; mt < 2; ++mt)
#pragma unroll
                    for (int j = 0; j < 4; ++j)
                        MMA_TF32(acc[mt][j], af[mt], bf[j][0], bf[j][1]);
            }
        }
#undef AISSUE

        const int hwBase = hw0 + wid * 32 + (lane & 3) * 2;
        float* actout = out + (size_t)N_IMG * M_POSE * HW;
#pragma unroll
        for (int mt = 0; mt < 2; ++mt) {
#pragma unroll
            for (int rr = 0; rr < 2; ++rr) {
                const int m = mt * 16 + (lane >> 2) + rr * 8;   // 0..31
                const float bias = g_bias[M_POSE + m];
                float* rowp = actout + ((size_t)img * (M_TOT - M_POSE) + m) * HW;
#pragma unroll
                for (int j = 0; j < 4; ++j) {
                    float2 v;
                    v.x = acc[mt][j][rr * 2 + 0] + bias;
                    v.y = acc[mt][j][rr * 2 + 1] + bias;
                    v.x = 1.f / (1.f + __expf(-v.x));
                    v.y = 1.f / (1.f + __expf(-v.y));
                    *reinterpret_cast<float2*>(rowp + hwBase + j * 8) = v;
                }
            }
        }
    }
#undef ISSUE_B
}

// ---------------- launch ----------------
extern "C" void kernel_launch(void* const* d_in, const int* in_sizes, int n_in,
                              void* d_out, int out_size) {
    const float* x  = (const float*)d_in[0];  // [64, 512, 32, 32]
    const float* Wp = (const float*)d_in[1];  // [512, 512]
    const float* bp = (const float*)d_in[2];  // [512]
    const float* Wa = (const float*)d_in[3];  // [32, 512]
    const float* ba = (const float*)d_in[4];  // [32]
    float* out = (float*)d_out;

    pack_w<<<(M_TOT * A_CH + 255) / 256, 256>>>(Wp, bp, Wa, ba);

    cudaFuncSetAttribute(caps_mma, cudaFuncAttributeMaxDynamicSharedMemorySize, SMEM_MAIN);
    caps_mma<<<dim3(5, HW / BN, N_IMG), 256, SMEM_MAIN>>>(x, out);
}